// round 11
// baseline (speedup 1.0000x reference)
#include <cuda_runtime.h>
#include <cstdint>

#define N_NODES  100000
#define D_MODEL  128
#define N_EDGES  1600000
#define HEADS    8
#define DHEAD    16

// ---------------- device scratch (no allocations allowed) ----------------
__device__ float g_q[N_NODES * D_MODEL];
__device__ float g_k[N_NODES * D_MODEL];
__device__ float g_v[N_NODES * D_MODEL];
__device__ int   g_count[N_NODES];
__device__ int   g_fill[N_NODES];
__device__ int   g_offsets[N_NODES + 1];
__device__ int   g_perm[N_EDGES];

// ---------------- init: zero dst histogram ----------------
__global__ void init_kernel(int n) {
    int idx = blockIdx.x * blockDim.x + threadIdx.x;
    if (idx < n) g_count[idx] = 0;
}

// ---------------- fused QKV GEMM: C[n,384] = x[n,128] @ [Wq|Wk|Wv] + bias ----------------
__global__ __launch_bounds__(256) void qkv_gemm_kernel(
    const float* __restrict__ x,
    const float* __restrict__ Wq, const float* __restrict__ bq,
    const float* __restrict__ Wk, const float* __restrict__ bk,
    const float* __restrict__ Wv, const float* __restrict__ bv,
    int n)
{
    __shared__ float As[64][65];
    __shared__ float Bs[64][64];

    const int tid = threadIdx.x;
    const int bm  = blockIdx.x * 64;
    const int sel = blockIdx.y >> 1;
    const int bn  = (blockIdx.y & 1) * 64;

    const float* W    = (sel == 0) ? Wq : (sel == 1 ? Wk : Wv);
    const float* bias = (sel == 0) ? bq : (sel == 1 ? bk : bv);
    float* Out        = (sel == 0) ? g_q : (sel == 1 ? g_k : g_v);

    const int tx = tid & 15;
    const int ty = tid >> 4;

    float acc[4][4];
#pragma unroll
    for (int i = 0; i < 4; i++)
#pragma unroll
        for (int j = 0; j < 4; j++) acc[i][j] = 0.f;

    for (int kk = 0; kk < 128; kk += 64) {
#pragma unroll
        for (int j = 0; j < 4; j++) {
            int i   = tid + j * 256;
            int row = i >> 4;
            int kc  = (i & 15) << 2;
            float4 a = make_float4(0.f, 0.f, 0.f, 0.f);
            if (bm + row < n)
                a = *(const float4*)(x + (size_t)(bm + row) * 128 + kk + kc);
            As[kc + 0][row] = a.x;
            As[kc + 1][row] = a.y;
            As[kc + 2][row] = a.z;
            As[kc + 3][row] = a.w;
        }
#pragma unroll
        for (int j = 0; j < 4; j++) {
            int i  = tid + j * 256;
            int k  = i >> 4;
            int cc = (i & 15) << 2;
            *(float4*)&Bs[k][cc] = *(const float4*)(W + (size_t)(kk + k) * 128 + bn + cc);
        }
        __syncthreads();

#pragma unroll 8
        for (int k = 0; k < 64; k++) {
            float a0 = As[k][ty * 4 + 0];
            float a1 = As[k][ty * 4 + 1];
            float a2 = As[k][ty * 4 + 2];
            float a3 = As[k][ty * 4 + 3];
            float4 b = *(const float4*)&Bs[k][tx * 4];
            acc[0][0] += a0 * b.x; acc[0][1] += a0 * b.y; acc[0][2] += a0 * b.z; acc[0][3] += a0 * b.w;
            acc[1][0] += a1 * b.x; acc[1][1] += a1 * b.y; acc[1][2] += a1 * b.z; acc[1][3] += a1 * b.w;
            acc[2][0] += a2 * b.x; acc[2][1] += a2 * b.y; acc[2][2] += a2 * b.z; acc[2][3] += a2 * b.w;
            acc[3][0] += a3 * b.x; acc[3][1] += a3 * b.y; acc[3][2] += a3 * b.z; acc[3][3] += a3 * b.w;
        }
        __syncthreads();
    }

    float4 bb = *(const float4*)(bias + bn + tx * 4);
#pragma unroll
    for (int i = 0; i < 4; i++) {
        int row = bm + ty * 4 + i;
        if (row < n) {
            float4 o;
            o.x = acc[i][0] + bb.x;
            o.y = acc[i][1] + bb.y;
            o.z = acc[i][2] + bb.z;
            o.w = acc[i][3] + bb.w;
            *(float4*)(Out + (size_t)row * 128 + bn + tx * 4) = o;
        }
    }
}

// ---------------- CSR build 1: histogram of dst ----------------
__global__ void hist_kernel(const int* __restrict__ dst, int E) {
    int e = blockIdx.x * blockDim.x + threadIdx.x;
    if (e < E) atomicAdd(&g_count[dst[e]], 1);
}

// ---------------- CSR build 2: exclusive scan (single block, 1024 threads) ----------------
__global__ __launch_bounds__(1024) void scan_kernel(int n) {
    __shared__ int sums[1024];
    const int t   = threadIdx.x;
    const int per = (n + 1023) / 1024;
    const int beg = t * per;
    const int end = min(beg + per, n);

    int s = 0;
    for (int i = beg; i < end; i++) s += g_count[i];
    sums[t] = s;
    __syncthreads();
    // Hillis-Steele inclusive scan (read, barrier, write, barrier)
    for (int off = 1; off < 1024; off <<= 1) {
        int v = (t >= off) ? sums[t - off] : 0;
        __syncthreads();
        sums[t] += v;
        __syncthreads();
    }
    int run = (t == 0) ? 0 : sums[t - 1];
    for (int i = beg; i < end; i++) {
        g_offsets[i] = run;
        g_fill[i]    = run;
        run += g_count[i];
    }
    if (t == 1023) g_offsets[n] = run;
}

// ---------------- CSR build 3: scatter edge ids into dst-grouped order ----------------
__global__ void scatter_kernel(const int* __restrict__ dst, int E) {
    int e = blockIdx.x * blockDim.x + threadIdx.x;
    if (e >= E) return;
    int pos = atomicAdd(&g_fill[dst[e]], 1);
    g_perm[pos] = e;
}

// ---------------- main: warp per destination node, no atomics ----------------
__global__ __launch_bounds__(256) void segment_kernel(
    const float* __restrict__ pi, const float* __restrict__ vw,
    const int* __restrict__ src,
    float* __restrict__ attn, float* __restrict__ node_out, int n)
{
    int node = (int)((blockIdx.x * (unsigned)blockDim.x + threadIdx.x) >> 5);
    int lane = threadIdx.x & 31;
    if (node >= n) return;

    const int beg = g_offsets[node];
    const int end = g_offsets[node + 1];

    // q row: loaded once per node
    float4 q4 = *(const float4*)(g_q + (size_t)node * 128 + lane * 4);

    // preload pi for this node's heads (leader lanes use it; all lanes load, cached)
    int h = lane >> 2;
    float pi0 = pi[(size_t)node * 24 + h * 3 + 0];
    float pi1 = pi[(size_t)node * 24 + h * 3 + 1];
    float pi2 = pi[(size_t)node * 24 + h * 3 + 2];

    float4 vacc = make_float4(0.f, 0.f, 0.f, 0.f);
    float ssum = 0.f;   // per lane: sum of its head's ex over the segment
    const int base16 = lane & 16;

    for (int base = beg; base < end; base += 32) {
        int cnt = min(32, end - base);
        int e_l = (lane < cnt) ? g_perm[base + lane] : 0;
        int s_l = (lane < cnt) ? src[e_l] : 0;
        for (int j = 0; j < cnt; j++) {
            int e = __shfl_sync(0xffffffffu, e_l, j);
            int s = __shfl_sync(0xffffffffu, s_l, j);

            float4 k4 = *(const float4*)(g_k + (size_t)s * 128 + lane * 4);
            float4 v4 = *(const float4*)(g_v + (size_t)s * 128 + lane * 4);

            float p = q4.x * k4.x + q4.y * k4.y + q4.z * k4.z + q4.w * k4.w;
            p += __shfl_xor_sync(0xffffffffu, p, 1);
            p += __shfl_xor_sync(0xffffffffu, p, 2);
            // lanes 4h..4h+3 hold head-h raw dot

            float ex = 0.f;
            if ((lane & 3) == 0) {
                float mix = pi0 * vw[(size_t)e * 3 + 0]
                          + pi1 * vw[(size_t)e * 3 + 1]
                          + pi2 * vw[(size_t)e * 3 + 2];
                if (mix > 0.f)
                    ex = __expf(p * 0.25f) * fmaxf(mix, 1e-8f);
            }
            // own head's ex on every lane
            float ah = __shfl_sync(0xffffffffu, ex, lane & 0x1C);
            vacc.x += ah * v4.x; vacc.y += ah * v4.y;
            vacc.z += ah * v4.z; vacc.w += ah * v4.w;
            ssum += ah;

            // store unnormalized attn (heads 0-3 by lane0, 4-7 by lane16)
            float e0 = __shfl_sync(0xffffffffu, ex, base16 + 0);
            float e1 = __shfl_sync(0xffffffffu, ex, base16 + 4);
            float e2 = __shfl_sync(0xffffffffu, ex, base16 + 8);
            float e3 = __shfl_sync(0xffffffffu, ex, base16 + 12);
            if ((lane & 15) == 0)
                *(float4*)(attn + (size_t)e * 8 + (lane >> 4) * 4) =
                    make_float4(e0, e1, e2, e3);
        }
    }

    // normalize + single store of the node row (zeros for empty segments)
    float inv = 1.f / fmaxf(ssum, 1e-8f);
    vacc.x *= inv; vacc.y *= inv; vacc.z *= inv; vacc.w *= inv;
    *(float4*)(node_out + (size_t)node * 128 + lane * 4) = vacc;

    // normalize attn: same lanes that wrote re-read (same-thread RAW, coherent)
    float i0 = __shfl_sync(0xffffffffu, inv, base16 + 0);
    float i1 = __shfl_sync(0xffffffffu, inv, base16 + 4);
    float i2 = __shfl_sync(0xffffffffu, inv, base16 + 8);
    float i3 = __shfl_sync(0xffffffffu, inv, base16 + 12);
    for (int base = beg; base < end; base += 32) {
        int cnt = min(32, end - base);
        int e_l = (lane < cnt) ? g_perm[base + lane] : 0;
        for (int j = 0; j < cnt; j++) {
            int e = __shfl_sync(0xffffffffu, e_l, j);
            if ((lane & 15) == 0) {
                float* ap = attn + (size_t)e * 8 + (lane >> 4) * 4;
                float4 a = *(float4*)ap;
                a.x *= i0; a.y *= i1; a.z *= i2; a.w *= i3;
                *(float4*)ap = a;
            }
        }
    }
}

// ---------------- launch ----------------
extern "C" void kernel_launch(void* const* d_in, const int* in_sizes, int n_in,
                              void* d_out, int out_size)
{
    const float* x  = (const float*)d_in[0];
    const float* pi = (const float*)d_in[1];
    const float* vw = (const float*)d_in[2];
    const float* Wq = (const float*)d_in[3];
    const float* bq = (const float*)d_in[4];
    const float* Wk = (const float*)d_in[5];
    const float* bk = (const float*)d_in[6];
    const float* Wv = (const float*)d_in[7];
    const float* bv = (const float*)d_in[8];
    const int* src  = (const int*)d_in[9];
    const int* dst  = (const int*)d_in[10];

    int n = in_sizes[0] / D_MODEL;
    int E = in_sizes[9];

    float* out_ns   = (float*)d_out;                    // [n, H, DH] = [n,128]
    float* out_attn = out_ns + (size_t)n * D_MODEL;     // [E, H]

    init_kernel<<<(n + 255) / 256, 256>>>(n);
    qkv_gemm_kernel<<<dim3((n + 63) / 64, 6), 256>>>(x, Wq, bq, Wk, bk, Wv, bv, n);
    hist_kernel<<<(E + 255) / 256, 256>>>(dst, E);
    scan_kernel<<<1, 1024>>>(n);
    scatter_kernel<<<(E + 255) / 256, 256>>>(dst, E);
    segment_kernel<<<(n * 32 + 255) / 256, 256>>>(pi, vw, src, out_attn, out_ns, n);
}

// round 12
// speedup vs baseline: 1.3766x; 1.3766x over previous
#include <cuda_runtime.h>
#include <cuda_bf16.h>
#include <cstdint>

#define N_NODES  100000
#define D_MODEL  128
#define N_EDGES  1600000
#define HEADS    8
#define DHEAD    16

// ---------------- device scratch (no allocations allowed) ----------------
__device__ float g_q[N_NODES * D_MODEL];
__device__ float g_k[N_NODES * D_MODEL];
__device__ float g_v[N_NODES * D_MODEL];
__device__ float g_ssum[N_NODES * HEADS];
// W split+transposed: [sel][n][k] bf16, hi and lo parts
__device__ __nv_bfloat16 g_wth[3 * 128 * 128];
__device__ __nv_bfloat16 g_wtl[3 * 128 * 128];

// ---------------- init: zero node accumulator + ssum ----------------
__global__ void init_kernel(float* __restrict__ node_out, int n) {
    int idx = blockIdx.x * blockDim.x + threadIdx.x;
    if (idx < n * D_MODEL) node_out[idx] = 0.f;
    if (idx < n * HEADS)   g_ssum[idx] = 0.f;
}

// ---------------- W convert: transpose + split fp32 -> bf16 hi/lo ----------------
__global__ void convert_w_kernel(const float* __restrict__ Wq,
                                 const float* __restrict__ Wk,
                                 const float* __restrict__ Wv) {
    int i = blockIdx.x * blockDim.x + threadIdx.x;
    if (i >= 3 * 128 * 128) return;
    int sel = i >> 14;
    int r   = i & 16383;
    int nn  = r >> 7;       // output col of W (= row of W^T)
    int kk  = r & 127;      // k index
    const float* W = (sel == 0) ? Wq : (sel == 1 ? Wk : Wv);
    float v = W[kk * 128 + nn];
    __nv_bfloat16 h = __float2bfloat16(v);
    g_wth[i] = h;
    g_wtl[i] = __float2bfloat16(v - __bfloat162float(h));
}

// ---------------- split-bf16 tensor-core QKV GEMM ----------------
// C[n,128(sel)] = x[n,128] @ W_sel + b_sel   via  xh*Wh + xh*Wl + xl*Wh
// block: 128(M) x 64(N), 8 warps (4x2), warp tile 32x32 = 2x4 m16n8 atoms.
// grid.y = 6: sel = y>>1, bn = (y&1)*64.
#define A_STRIDE 40   // 32 k + 8 pad bf16: bank-conflict-free fragment loads
__device__ __forceinline__ void mma_bf16(float* c, const uint32_t* a, const uint32_t* b) {
    asm volatile(
        "mma.sync.aligned.m16n8k16.row.col.f32.bf16.bf16.f32 "
        "{%0,%1,%2,%3}, {%4,%5,%6,%7}, {%8,%9}, {%0,%1,%2,%3};\n"
        : "+f"(c[0]), "+f"(c[1]), "+f"(c[2]), "+f"(c[3])
        : "r"(a[0]), "r"(a[1]), "r"(a[2]), "r"(a[3]), "r"(b[0]), "r"(b[1]));
}

__global__ __launch_bounds__(256) void qkv_mma_kernel(
    const float* __restrict__ x,
    const float* __restrict__ bq, const float* __restrict__ bk,
    const float* __restrict__ bv, int n)
{
    __shared__ __nv_bfloat16 Ah[128][A_STRIDE];
    __shared__ __nv_bfloat16 Al[128][A_STRIDE];
    __shared__ __nv_bfloat16 Bh[64][A_STRIDE];
    __shared__ __nv_bfloat16 Bl[64][A_STRIDE];

    const int tid  = threadIdx.x;
    const int warp = tid >> 5;
    const int lane = tid & 31;
    const int bm   = blockIdx.x * 128;
    const int sel  = blockIdx.y >> 1;
    const int bn   = (blockIdx.y & 1) * 64;

    float* Out        = (sel == 0) ? g_q : (sel == 1 ? g_k : g_v);
    const float* bias = (sel == 0) ? bq : (sel == 1 ? bk : bv);
    const __nv_bfloat16* Wth = g_wth + sel * 16384;
    const __nv_bfloat16* Wtl = g_wtl + sel * 16384;

    const int wm = (warp & 3) * 32;    // warp m offset
    const int wn = (warp >> 2) * 32;   // warp n offset

    float acc[2][4][4];
#pragma unroll
    for (int i = 0; i < 2; i++)
#pragma unroll
        for (int j = 0; j < 4; j++)
#pragma unroll
            for (int t = 0; t < 4; t++) acc[i][j][t] = 0.f;

    const int r  = lane >> 2;          // 0..7
    const int c2 = (lane & 3) * 2;     // 0,2,4,6

    for (int kc = 0; kc < 128; kc += 32) {
        // ---- A fill: 128 rows x 32 k, fp32 -> split bf16 ----
#pragma unroll
        for (int it = 0; it < 4; it++) {
            int i   = tid + it * 256;      // 0..1023
            int row = i >> 3;
            int sg  = i & 7;               // float4 segment
            float4 v = make_float4(0.f, 0.f, 0.f, 0.f);
            if (bm + row < n)
                v = *(const float4*)(x + (size_t)(bm + row) * 128 + kc + sg * 4);
            __nv_bfloat16 h0 = __float2bfloat16(v.x), h1 = __float2bfloat16(v.y);
            __nv_bfloat16 h2 = __float2bfloat16(v.z), h3 = __float2bfloat16(v.w);
            Ah[row][sg*4+0] = h0; Ah[row][sg*4+1] = h1;
            Ah[row][sg*4+2] = h2; Ah[row][sg*4+3] = h3;
            Al[row][sg*4+0] = __float2bfloat16(v.x - __bfloat162float(h0));
            Al[row][sg*4+1] = __float2bfloat16(v.y - __bfloat162float(h1));
            Al[row][sg*4+2] = __float2bfloat16(v.z - __bfloat162float(h2));
            Al[row][sg*4+3] = __float2bfloat16(v.w - __bfloat162float(h3));
        }
        // ---- B fill: 64 n-rows x 32 k from pre-transposed W ----
        {
            int nn = tid >> 2;             // 0..63
            int sg = tid & 3;              // uint4 segment (8 bf16)
            *(uint4*)&Bh[nn][sg*8] = *(const uint4*)(Wth + (size_t)(bn + nn) * 128 + kc + sg * 8);
            *(uint4*)&Bl[nn][sg*8] = *(const uint4*)(Wtl + (size_t)(bn + nn) * 128 + kc + sg * 8);
        }
        __syncthreads();

#pragma unroll
        for (int ks = 0; ks < 2; ks++) {
            int k0 = ks * 16;
            uint32_t ah[2][4], al[2][4], bh[4][2], bl[4][2];
#pragma unroll
            for (int ma = 0; ma < 2; ma++) {
                int rb = wm + ma * 16;
                ah[ma][0] = *(const uint32_t*)&Ah[rb + r    ][k0 + c2    ];
                ah[ma][1] = *(const uint32_t*)&Ah[rb + r + 8][k0 + c2    ];
                ah[ma][2] = *(const uint32_t*)&Ah[rb + r    ][k0 + c2 + 8];
                ah[ma][3] = *(const uint32_t*)&Ah[rb + r + 8][k0 + c2 + 8];
                al[ma][0] = *(const uint32_t*)&Al[rb + r    ][k0 + c2    ];
                al[ma][1] = *(const uint32_t*)&Al[rb + r + 8][k0 + c2    ];
                al[ma][2] = *(const uint32_t*)&Al[rb + r    ][k0 + c2 + 8];
                al[ma][3] = *(const uint32_t*)&Al[rb + r + 8][k0 + c2 + 8];
            }
#pragma unroll
            for (int nb = 0; nb < 4; nb++) {
                int nbase = wn + nb * 8 + r;
                bh[nb][0] = *(const uint32_t*)&Bh[nbase][k0 + c2    ];
                bh[nb][1] = *(const uint32_t*)&Bh[nbase][k0 + c2 + 8];
                bl[nb][0] = *(const uint32_t*)&Bl[nbase][k0 + c2    ];
                bl[nb][1] = *(const uint32_t*)&Bl[nbase][k0 + c2 + 8];
            }
#pragma unroll
            for (int ma = 0; ma < 2; ma++)
#pragma unroll
                for (int nb = 0; nb < 4; nb++) {
                    mma_bf16(acc[ma][nb], ah[ma], bh[nb]);
                    mma_bf16(acc[ma][nb], ah[ma], bl[nb]);
                    mma_bf16(acc[ma][nb], al[ma], bh[nb]);
                }
        }
        __syncthreads();
    }

    // ---- epilogue: add bias, store fp32 ----
#pragma unroll
    for (int ma = 0; ma < 2; ma++)
#pragma unroll
        for (int nb = 0; nb < 4; nb++) {
            int gcol = bn + wn + nb * 8 + c2;
            float b0 = bias[gcol], b1 = bias[gcol + 1];
            int row0 = bm + wm + ma * 16 + r;
            if (row0 < n) {
                float2 o = make_float2(acc[ma][nb][0] + b0, acc[ma][nb][1] + b1);
                *(float2*)(Out + (size_t)row0 * 128 + gcol) = o;
            }
            int row1 = row0 + 8;
            if (row1 < n) {
                float2 o = make_float2(acc[ma][nb][2] + b0, acc[ma][nb][3] + b1);
                *(float2*)(Out + (size_t)row1 * 128 + gcol) = o;
            }
        }
}

// ---------------- single fused edge sweep (warp per edge) ----------------
__global__ __launch_bounds__(256) void edge_fused_kernel(
    const float* __restrict__ pi, const float* __restrict__ vw,
    const int* __restrict__ src, const int* __restrict__ dst,
    float* __restrict__ attn_out, float* __restrict__ node_out, int E)
{
    int warp = (int)((blockIdx.x * (unsigned)blockDim.x + threadIdx.x) >> 5);
    int lane = threadIdx.x & 31;
    if (warp >= E) return;
    int s = src[warp];
    int d = dst[warp];

    float4 q4 = *(const float4*)(g_q + (size_t)d * 128 + lane * 4);
    float4 k4 = *(const float4*)(g_k + (size_t)s * 128 + lane * 4);
    float4 v4 = *(const float4*)(g_v + (size_t)s * 128 + lane * 4);

    float p = q4.x * k4.x + q4.y * k4.y + q4.z * k4.z + q4.w * k4.w;
    p += __shfl_xor_sync(0xffffffffu, p, 1);
    p += __shfl_xor_sync(0xffffffffu, p, 2);

    float ex = 0.f;
    if ((lane & 3) == 0) {
        int h = lane >> 2;
        float mix = 0.f;
#pragma unroll
        for (int m = 0; m < 3; m++)
            mix += pi[(size_t)d * 24 + h * 3 + m] * vw[(size_t)warp * 3 + m];
        if (mix > 0.f)
            ex = __expf(p * 0.25f) * fmaxf(mix, 1e-8f);
    }

    float ah = __shfl_sync(0xffffffffu, ex, lane & 0x1C);

    int base = lane & 16;
    float e0 = __shfl_sync(0xffffffffu, ex, base + 0);
    float e1 = __shfl_sync(0xffffffffu, ex, base + 4);
    float e2 = __shfl_sync(0xffffffffu, ex, base + 8);
    float e3 = __shfl_sync(0xffffffffu, ex, base + 12);
    if ((lane & 15) == 0) {
        int off = (lane >> 4) * 4;
        *(float4*)(attn_out + (size_t)warp * 8 + off) = make_float4(e0, e1, e2, e3);
        float* sp = g_ssum + (size_t)d * 8 + off;
        asm volatile("red.global.add.v4.f32 [%0], {%1, %2, %3, %4};"
                     :: "l"(sp), "f"(e0), "f"(e1), "f"(e2), "f"(e3)
                     : "memory");
    }

    float* dp = node_out + (size_t)d * 128 + lane * 4;
    asm volatile("red.global.add.v4.f32 [%0], {%1, %2, %3, %4};"
                 :: "l"(dp), "f"(v4.x * ah), "f"(v4.y * ah), "f"(v4.z * ah), "f"(v4.w * ah)
                 : "memory");
}

// ---------------- epilogue 1: node_out /= max(ssum, 1e-8) ----------------
__global__ void node_norm_kernel(float* __restrict__ node_out, int n) {
    int idx = blockIdx.x * blockDim.x + threadIdx.x;
    if (idx >= n * 32) return;
    int node = idx >> 5;
    int h    = (idx >> 2) & 7;
    float ss = g_ssum[(size_t)node * 8 + h];
    float inv = 1.f / fmaxf(ss, 1e-8f);
    float4 v = *(float4*)(node_out + (size_t)idx * 4);
    v.x *= inv; v.y *= inv; v.z *= inv; v.w *= inv;
    *(float4*)(node_out + (size_t)idx * 4) = v;
}

// ---------------- epilogue 2: attn normalize ----------------
__global__ void attn_norm_kernel(const int* __restrict__ dst,
                                 float* __restrict__ attn, int E) {
    int e = blockIdx.x * blockDim.x + threadIdx.x;
    if (e >= E) return;
    int d = dst[e];
    float4 s0 = *(const float4*)(g_ssum + (size_t)d * 8);
    float4 s1 = *(const float4*)(g_ssum + (size_t)d * 8 + 4);
    float4 a0 = *(float4*)(attn + (size_t)e * 8);
    float4 a1 = *(float4*)(attn + (size_t)e * 8 + 4);
    a0.x /= fmaxf(s0.x, 1e-8f); a0.y /= fmaxf(s0.y, 1e-8f);
    a0.z /= fmaxf(s0.z, 1e-8f); a0.w /= fmaxf(s0.w, 1e-8f);
    a1.x /= fmaxf(s1.x, 1e-8f); a1.y /= fmaxf(s1.y, 1e-8f);
    a1.z /= fmaxf(s1.z, 1e-8f); a1.w /= fmaxf(s1.w, 1e-8f);
    *(float4*)(attn + (size_t)e * 8)     = a0;
    *(float4*)(attn + (size_t)e * 8 + 4) = a1;
}

// ---------------- launch ----------------
extern "C" void kernel_launch(void* const* d_in, const int* in_sizes, int n_in,
                              void* d_out, int out_size)
{
    const float* x  = (const float*)d_in[0];
    const float* pi = (const float*)d_in[1];
    const float* vw = (const float*)d_in[2];
    const float* Wq = (const float*)d_in[3];
    const float* bq = (const float*)d_in[4];
    const float* Wk = (const float*)d_in[5];
    const float* bk = (const float*)d_in[6];
    const float* Wv = (const float*)d_in[7];
    const float* bv = (const float*)d_in[8];
    const int* src  = (const int*)d_in[9];
    const int* dst  = (const int*)d_in[10];

    int n = in_sizes[0] / D_MODEL;
    int E = in_sizes[9];

    float* out_ns   = (float*)d_out;                    // [n, H, DH] = [n,128]
    float* out_attn = out_ns + (size_t)n * D_MODEL;     // [E, H]

    init_kernel<<<(n * D_MODEL + 255) / 256, 256>>>(out_ns, n);
    convert_w_kernel<<<(3 * 16384 + 255) / 256, 256>>>(Wq, Wk, Wv);
    qkv_mma_kernel<<<dim3((n + 127) / 128, 6), 256>>>(x, bq, bk, bv, n);
    edge_fused_kernel<<<(E + 7) / 8, 256>>>(pi, vw, src, dst, out_attn, out_ns, E);
    node_norm_kernel<<<(n * 32 + 255) / 256, 256>>>(out_ns, n);
    attn_norm_kernel<<<(E + 255) / 256, 256>>>(dst, out_attn, E);
}

// round 17
// speedup vs baseline: 1.6197x; 1.1766x over previous
#include <cuda_runtime.h>
#include <cuda_bf16.h>
#include <cuda_fp16.h>
#include <cstdint>

#define N_NODES  100000
#define D_MODEL  128
#define N_EDGES  1600000
#define HEADS    8
#define DHEAD    16

// ---------------- device scratch (no allocations allowed) ----------------
// q/k/v stored fp16: 3 * 25.6 MB = 76.8 MB -> L2-resident gather working set
__device__ __half g_q[N_NODES * D_MODEL];
__device__ __half g_k[N_NODES * D_MODEL];
__device__ __half g_v[N_NODES * D_MODEL];
__device__ float  g_ssum[N_NODES * HEADS];
// W split+transposed: [sel][n][k] bf16, hi and lo parts
__device__ __nv_bfloat16 g_wth[3 * 128 * 128];
__device__ __nv_bfloat16 g_wtl[3 * 128 * 128];

// ---------------- init: zero node accumulator + ssum ----------------
__global__ void init_kernel(float* __restrict__ node_out, int n) {
    int idx = blockIdx.x * blockDim.x + threadIdx.x;
    if (idx < n * D_MODEL) node_out[idx] = 0.f;
    if (idx < n * HEADS)   g_ssum[idx] = 0.f;
}

// ---------------- W convert: transpose + split fp32 -> bf16 hi/lo ----------------
__global__ void convert_w_kernel(const float* __restrict__ Wq,
                                 const float* __restrict__ Wk,
                                 const float* __restrict__ Wv) {
    int i = blockIdx.x * blockDim.x + threadIdx.x;
    if (i >= 3 * 128 * 128) return;
    int sel = i >> 14;
    int r   = i & 16383;
    int nn  = r >> 7;
    int kk  = r & 127;
    const float* W = (sel == 0) ? Wq : (sel == 1 ? Wk : Wv);
    float v = W[kk * 128 + nn];
    __nv_bfloat16 h = __float2bfloat16(v);
    g_wth[i] = h;
    g_wtl[i] = __float2bfloat16(v - __bfloat162float(h));
}

// ---------------- split-bf16 tensor-core QKV GEMM, fp16 output ----------------
#define A_STRIDE 40
__device__ __forceinline__ void mma_bf16(float* c, const uint32_t* a, const uint32_t* b) {
    asm volatile(
        "mma.sync.aligned.m16n8k16.row.col.f32.bf16.bf16.f32 "
        "{%0,%1,%2,%3}, {%4,%5,%6,%7}, {%8,%9}, {%0,%1,%2,%3};\n"
        : "+f"(c[0]), "+f"(c[1]), "+f"(c[2]), "+f"(c[3])
        : "r"(a[0]), "r"(a[1]), "r"(a[2]), "r"(a[3]), "r"(b[0]), "r"(b[1]));
}

__global__ __launch_bounds__(256) void qkv_mma_kernel(
    const float* __restrict__ x,
    const float* __restrict__ bq, const float* __restrict__ bk,
    const float* __restrict__ bv, int n)
{
    __shared__ __nv_bfloat16 Ah[128][A_STRIDE];
    __shared__ __nv_bfloat16 Al[128][A_STRIDE];
    __shared__ __nv_bfloat16 Bh[64][A_STRIDE];
    __shared__ __nv_bfloat16 Bl[64][A_STRIDE];

    const int tid  = threadIdx.x;
    const int warp = tid >> 5;
    const int lane = tid & 31;
    const int bm   = blockIdx.x * 128;
    const int sel  = blockIdx.y >> 1;
    const int bn   = (blockIdx.y & 1) * 64;

    __half* Out       = (sel == 0) ? g_q : (sel == 1 ? g_k : g_v);
    const float* bias = (sel == 0) ? bq : (sel == 1 ? bk : bv);
    const __nv_bfloat16* Wth = g_wth + sel * 16384;
    const __nv_bfloat16* Wtl = g_wtl + sel * 16384;

    const int wm = (warp & 3) * 32;
    const int wn = (warp >> 2) * 32;

    float acc[2][4][4];
#pragma unroll
    for (int i = 0; i < 2; i++)
#pragma unroll
        for (int j = 0; j < 4; j++)
#pragma unroll
            for (int t = 0; t < 4; t++) acc[i][j][t] = 0.f;

    const int r  = lane >> 2;
    const int c2 = (lane & 3) * 2;

    for (int kc = 0; kc < 128; kc += 32) {
#pragma unroll
        for (int it = 0; it < 4; it++) {
            int i   = tid + it * 256;
            int row = i >> 3;
            int sg  = i & 7;
            float4 v = make_float4(0.f, 0.f, 0.f, 0.f);
            if (bm + row < n)
                v = *(const float4*)(x + (size_t)(bm + row) * 128 + kc + sg * 4);
            __nv_bfloat16 h0 = __float2bfloat16(v.x), h1 = __float2bfloat16(v.y);
            __nv_bfloat16 h2 = __float2bfloat16(v.z), h3 = __float2bfloat16(v.w);
            Ah[row][sg*4+0] = h0; Ah[row][sg*4+1] = h1;
            Ah[row][sg*4+2] = h2; Ah[row][sg*4+3] = h3;
            Al[row][sg*4+0] = __float2bfloat16(v.x - __bfloat162float(h0));
            Al[row][sg*4+1] = __float2bfloat16(v.y - __bfloat162float(h1));
            Al[row][sg*4+2] = __float2bfloat16(v.z - __bfloat162float(h2));
            Al[row][sg*4+3] = __float2bfloat16(v.w - __bfloat162float(h3));
        }
        {
            int nn = tid >> 2;
            int sg = tid & 3;
            *(uint4*)&Bh[nn][sg*8] = *(const uint4*)(Wth + (size_t)(bn + nn) * 128 + kc + sg * 8);
            *(uint4*)&Bl[nn][sg*8] = *(const uint4*)(Wtl + (size_t)(bn + nn) * 128 + kc + sg * 8);
        }
        __syncthreads();

#pragma unroll
        for (int ks = 0; ks < 2; ks++) {
            int k0 = ks * 16;
            uint32_t ah[2][4], al[2][4], bh[4][2], bl[4][2];
#pragma unroll
            for (int ma = 0; ma < 2; ma++) {
                int rb = wm + ma * 16;
                ah[ma][0] = *(const uint32_t*)&Ah[rb + r    ][k0 + c2    ];
                ah[ma][1] = *(const uint32_t*)&Ah[rb + r + 8][k0 + c2    ];
                ah[ma][2] = *(const uint32_t*)&Ah[rb + r    ][k0 + c2 + 8];
                ah[ma][3] = *(const uint32_t*)&Ah[rb + r + 8][k0 + c2 + 8];
                al[ma][0] = *(const uint32_t*)&Al[rb + r    ][k0 + c2    ];
                al[ma][1] = *(const uint32_t*)&Al[rb + r + 8][k0 + c2    ];
                al[ma][2] = *(const uint32_t*)&Al[rb + r    ][k0 + c2 + 8];
                al[ma][3] = *(const uint32_t*)&Al[rb + r + 8][k0 + c2 + 8];
            }
#pragma unroll
            for (int nb = 0; nb < 4; nb++) {
                int nbase = wn + nb * 8 + r;
                bh[nb][0] = *(const uint32_t*)&Bh[nbase][k0 + c2    ];
                bh[nb][1] = *(const uint32_t*)&Bh[nbase][k0 + c2 + 8];
                bl[nb][0] = *(const uint32_t*)&Bl[nbase][k0 + c2    ];
                bl[nb][1] = *(const uint32_t*)&Bl[nbase][k0 + c2 + 8];
            }
#pragma unroll
            for (int ma = 0; ma < 2; ma++)
#pragma unroll
                for (int nb = 0; nb < 4; nb++) {
                    mma_bf16(acc[ma][nb], ah[ma], bh[nb]);
                    mma_bf16(acc[ma][nb], ah[ma], bl[nb]);
                    mma_bf16(acc[ma][nb], al[ma], bh[nb]);
                }
        }
        __syncthreads();
    }

    // ---- epilogue: add bias, store fp16 ----
#pragma unroll
    for (int ma = 0; ma < 2; ma++)
#pragma unroll
        for (int nb = 0; nb < 4; nb++) {
            int gcol = bn + wn + nb * 8 + c2;
            float b0 = bias[gcol], b1 = bias[gcol + 1];
            int row0 = bm + wm + ma * 16 + r;
            if (row0 < n) {
                __half2 o = __floats2half2_rn(acc[ma][nb][0] + b0, acc[ma][nb][1] + b1);
                *(__half2*)(Out + (size_t)row0 * 128 + gcol) = o;
            }
            int row1 = row0 + 8;
            if (row1 < n) {
                __half2 o = __floats2half2_rn(acc[ma][nb][2] + b0, acc[ma][nb][3] + b1);
                *(__half2*)(Out + (size_t)row1 * 128 + gcol) = o;
            }
        }
}

// ---------------- single fused edge sweep (warp per edge), fp16 gathers ----------------
__global__ __launch_bounds__(256) void edge_fused_kernel(
    const float* __restrict__ pi, const float* __restrict__ vw,
    const int* __restrict__ src, const int* __restrict__ dst,
    float* __restrict__ attn_out, float* __restrict__ node_out, int E)
{
    int warp = (int)((blockIdx.x * (unsigned)blockDim.x + threadIdx.x) >> 5);
    int lane = threadIdx.x & 31;
    if (warp >= E) return;
    int s = src[warp];
    int d = dst[warp];

    // 8-byte gathers (4 halves per lane), issued back-to-back for MLP
    uint2 qu = *(const uint2*)(g_q + (size_t)d * 128 + lane * 4);
    uint2 ku = *(const uint2*)(g_k + (size_t)s * 128 + lane * 4);
    uint2 vu = *(const uint2*)(g_v + (size_t)s * 128 + lane * 4);

    __half2* qh = (__half2*)&qu;
    __half2* kh = (__half2*)&ku;
    __half2* vh = (__half2*)&vu;
    float2 q0 = __half22float2(qh[0]), q1 = __half22float2(qh[1]);
    float2 k0 = __half22float2(kh[0]), k1 = __half22float2(kh[1]);
    float2 v0 = __half22float2(vh[0]), v1 = __half22float2(vh[1]);

    float p = q0.x * k0.x + q0.y * k0.y + q1.x * k1.x + q1.y * k1.y;
    p += __shfl_xor_sync(0xffffffffu, p, 1);
    p += __shfl_xor_sync(0xffffffffu, p, 2);
    // lanes 4h..4h+3 hold head-h raw dot

    float ex = 0.f;
    if ((lane & 3) == 0) {
        int h = lane >> 2;
        float mix = 0.f;
#pragma unroll
        for (int m = 0; m < 3; m++)
            mix += pi[(size_t)d * 24 + h * 3 + m] * vw[(size_t)warp * 3 + m];
        if (mix > 0.f)
            ex = __expf(p * 0.25f) * fmaxf(mix, 1e-8f);
    }

    float ah = __shfl_sync(0xffffffffu, ex, lane & 0x1C);

    int base = lane & 16;
    float e0 = __shfl_sync(0xffffffffu, ex, base + 0);
    float e1 = __shfl_sync(0xffffffffu, ex, base + 4);
    float e2 = __shfl_sync(0xffffffffu, ex, base + 8);
    float e3 = __shfl_sync(0xffffffffu, ex, base + 12);
    if ((lane & 15) == 0) {
        int off = (lane >> 4) * 4;
        *(float4*)(attn_out + (size_t)warp * 8 + off) = make_float4(e0, e1, e2, e3);
        float* sp = g_ssum + (size_t)d * 8 + off;
        asm volatile("red.global.add.v4.f32 [%0], {%1, %2, %3, %4};"
                     :: "l"(sp), "f"(e0), "f"(e1), "f"(e2), "f"(e3)
                     : "memory");
    }

    float* dp = node_out + (size_t)d * 128 + lane * 4;
    asm volatile("red.global.add.v4.f32 [%0], {%1, %2, %3, %4};"
                 :: "l"(dp), "f"(v0.x * ah), "f"(v0.y * ah), "f"(v1.x * ah), "f"(v1.y * ah)
                 : "memory");
}

// ---------------- epilogue 1: node_out /= max(ssum, 1e-8) ----------------
__global__ void node_norm_kernel(float* __restrict__ node_out, int n) {
    int idx = blockIdx.x * blockDim.x + threadIdx.x;
    if (idx >= n * 32) return;
    int node = idx >> 5;
    int h    = (idx >> 2) & 7;
    float ss = g_ssum[(size_t)node * 8 + h];
    float inv = 1.f / fmaxf(ss, 1e-8f);
    float4 v = *(float4*)(node_out + (size_t)idx * 4);
    v.x *= inv; v.y *= inv; v.z *= inv; v.w *= inv;
    *(float4*)(node_out + (size_t)idx * 4) = v;
}

// ---------------- epilogue 2: attn normalize ----------------
__global__ void attn_norm_kernel(const int* __restrict__ dst,
                                 float* __restrict__ attn, int E) {
    int e = blockIdx.x * blockDim.x + threadIdx.x;
    if (e >= E) return;
    int d = dst[e];
    float4 s0 = *(const float4*)(g_ssum + (size_t)d * 8);
    float4 s1 = *(const float4*)(g_ssum + (size_t)d * 8 + 4);
    float4 a0 = *(float4*)(attn + (size_t)e * 8);
    float4 a1 = *(float4*)(attn + (size_t)e * 8 + 4);
    a0.x /= fmaxf(s0.x, 1e-8f); a0.y /= fmaxf(s0.y, 1e-8f);
    a0.z /= fmaxf(s0.z, 1e-8f); a0.w /= fmaxf(s0.w, 1e-8f);
    a1.x /= fmaxf(s1.x, 1e-8f); a1.y /= fmaxf(s1.y, 1e-8f);
    a1.z /= fmaxf(s1.z, 1e-8f); a1.w /= fmaxf(s1.w, 1e-8f);
    *(float4*)(attn + (size_t)e * 8)     = a0;
    *(float4*)(attn + (size_t)e * 8 + 4) = a1;
}

// ---------------- launch ----------------
extern "C" void kernel_launch(void* const* d_in, const int* in_sizes, int n_in,
                              void* d_out, int out_size)
{
    const float* x  = (const float*)d_in[0];
    const float* pi = (const float*)d_in[1];
    const float* vw = (const float*)d_in[2];
    const float* Wq = (const float*)d_in[3];
    const float* bq = (const float*)d_in[4];
    const float* Wk = (const float*)d_in[5];
    const float* bk = (const float*)d_in[6];
    const float* Wv = (const float*)d_in[7];
    const float* bv = (const float*)d_in[8];
    const int* src  = (const int*)d_in[9];
    const int* dst  = (const int*)d_in[10];

    int n = in_sizes[0] / D_MODEL;
    int E = in_sizes[9];

    float* out_ns   = (float*)d_out;                    // [n, H, DH] = [n,128]
    float* out_attn = out_ns + (size_t)n * D_MODEL;     // [E, H]

    init_kernel<<<(n * D_MODEL + 255) / 256, 256>>>(out_ns, n);
    convert_w_kernel<<<(3 * 16384 + 255) / 256, 256>>>(Wq, Wk, Wv);
    qkv_mma_kernel<<<dim3((n + 127) / 128, 6), 256>>>(x, bq, bk, bv, n);
    edge_fused_kernel<<<(E + 7) / 8, 256>>>(pi, vw, src, dst, out_attn, out_ns, E);
    node_norm_kernel<<<(n * 32 + 255) / 256, 256>>>(out_ns, n);
    attn_norm_kernel<<<(E + 255) / 256, 256>>>(dst, out_attn, E);
}